// round 6
// baseline (speedup 1.0000x reference)
#include <cuda_runtime.h>
#include <cstdint>

// Shapes (fixed by the problem)
#define BB   32
#define SS   128
#define VV   8192
#define EE   256
#define MR   (BB*SS)

// G1 split-K config
#define KSPLIT 8
#define KCHUNK (VV/KSPLIT)   // 1024
#define STR    20            // smem row stride in uint32 (16 + 4 pad)

// ---------------- scratch (device globals; no allocation) ----------------
__device__ float g_p1[KSPLIT][MR][EE];  // G1 split-K partials 32 MB
__device__ float g_h[MR*EE];            // h     [4096,256]
__device__ float g_s[MR];               // rowsum(h)
__device__ float g_weff[BB*EE*EE];      // Weff  [32,256,256]
__device__ float g_y[MR*EE];            // y     [4096,256]
__device__ float g_part[64*BB*EE];      // G4 split-K partials
__device__ float g_y2[BB*EE];           // y2    [32,256]

// ---------------- helpers ----------------
__device__ __forceinline__ uint32_t f2tf32(float f) {
    uint32_t u;
    asm("cvt.rna.tf32.f32 %0, %1;" : "=r"(u) : "f"(f));
    return u;
}

__device__ __forceinline__ uint32_t smem_u32(const void* p) {
    uint32_t a;
    asm("{ .reg .u64 t; cvta.to.shared.u64 t, %1; cvt.u32.u64 %0, t; }" : "=r"(a) : "l"(p));
    return a;
}

__device__ __forceinline__ uint4 ldsm_x4(uint32_t addr) {
    uint4 r;
    asm volatile("ldmatrix.sync.aligned.m8n8.x4.shared.b16 {%0,%1,%2,%3}, [%4];"
        : "=r"(r.x), "=r"(r.y), "=r"(r.z), "=r"(r.w) : "r"(addr));
    return r;
}

__device__ __forceinline__ void mma_tf32(float c[4], const uint32_t a[4], const uint32_t b[2]) {
    asm volatile(
        "mma.sync.aligned.m16n8k8.row.col.f32.tf32.tf32.f32 "
        "{%0,%1,%2,%3}, {%4,%5,%6,%7}, {%8,%9}, {%0,%1,%2,%3};"
        : "+f"(c[0]), "+f"(c[1]), "+f"(c[2]), "+f"(c[3])
        : "r"(a[0]), "r"(a[1]), "r"(a[2]), "r"(a[3]), "r"(b[0]), "r"(b[1]));
}

// profile-slot shifter (3 launches before g1 so ncu's fixed skip lands on g1)
__global__ void dummy_kernel() {}

// ===================================================================
// G1 split-K: partial[kz] = x[:, kz*1024:+1024] @ w_emb^T chunk
// Block tile 128m x 64n, BK=16, 256 threads = 8 warps (4m x 2n),
// warp tile 32x32 (acc=32 regs -> ~85 regs total, 3 CTAs/SM).
// grid (4=n, 32=m, 8=kz) = 1024 CTAs.
// ===================================================================
__global__ void __launch_bounds__(256, 3) g1_kernel(
    const float* __restrict__ x, const float* __restrict__ w_emb)
{
    __shared__ uint32_t sA[2][128 * STR];   // 10 KB x2
    __shared__ uint32_t sB[2][64 * STR];    // 5 KB x2

    const int tid  = threadIdx.x;
    const int lane = tid & 31;
    const int warp = tid >> 5;
    const int wm = (warp >> 1) * 32;        // 0,32,64,96
    const int wn = (warp & 1) * 32;         // 0,32
    const long bm = (long)blockIdx.y * 128;
    const long bn = (long)blockIdx.x * 64;
    const long kbase = (long)blockIdx.z * KCHUNK;

    // A staging: row = tid>>1 (0..127), half = (tid&1)*8 -> two float4
    // B staging: row = tid>>2 (0..63), quarter = (tid&3)*4 -> one float4
    const int sarow = tid >> 1;
    const int sacol = (tid & 1) * 8;
    const int sbrow = tid >> 2;
    const int sbcol = (tid & 3) * 4;
    const float* Arow = x + (bm + sarow) * VV + kbase + sacol;
    const float* Brow = w_emb + (bn + sbrow) * VV + kbase + sbcol;

    const uint32_t sAb[2] = { smem_u32(&sA[0][0]), smem_u32(&sA[1][0]) };
    const uint32_t sBb[2] = { smem_u32(&sB[0][0]), smem_u32(&sB[1][0]) };

    // ldmatrix per-lane row/col offsets (mapping validated in R5)
    const int aRow = ((lane >> 3) & 1) * 8 + (lane & 7);
    const int aCol = (lane >> 4) * 4;
    const int bRow = ((lane >> 4) & 1) * 8 + (lane & 7);
    const int bCol = ((lane >> 3) & 1) * 4;

    float acc[2][4][4] = {};
    float4 pa[2], pb;

    // prefetch + stage tile 0
    #pragma unroll
    for (int q = 0; q < 2; q++) pa[q] = *reinterpret_cast<const float4*>(Arow + q * 4);
    pb = *reinterpret_cast<const float4*>(Brow);
    #pragma unroll
    for (int q = 0; q < 2; q++) {
        uint4 au = { f2tf32(pa[q].x), f2tf32(pa[q].y), f2tf32(pa[q].z), f2tf32(pa[q].w) };
        *reinterpret_cast<uint4*>(&sA[0][sarow * STR + sacol + q * 4]) = au;
    }
    {
        uint4 bu = { f2tf32(pb.x), f2tf32(pb.y), f2tf32(pb.z), f2tf32(pb.w) };
        *reinterpret_cast<uint4*>(&sB[0][sbrow * STR + sbcol]) = bu;
    }
    __syncthreads();

    const int nkt = KCHUNK / 16;            // 64
    for (int kt = 0; kt < nkt; kt++) {
        const int cur = kt & 1;
        const bool more = (kt + 1) < nkt;

        if (more) {
            const float* Ap = Arow + (kt + 1) * 16;
            const float* Bp = Brow + (kt + 1) * 16;
            #pragma unroll
            for (int q = 0; q < 2; q++) pa[q] = *reinterpret_cast<const float4*>(Ap + q * 4);
            pb = *reinterpret_cast<const float4*>(Bp);
        }

        const uint32_t ab = sAb[cur];
        const uint32_t bb = sBb[cur];
        #pragma unroll
        for (int ks = 0; ks < 2; ks++) {
            const int k0 = ks * 8;
            uint4 af[2], bf[2];
            #pragma unroll
            for (int mt = 0; mt < 2; mt++)
                af[mt] = ldsm_x4(ab + ((wm + mt * 16 + aRow) * STR + k0 + aCol) * 4);
            #pragma unroll
            for (int q = 0; q < 2; q++)
                bf[q] = ldsm_x4(bb + ((wn + q * 16 + bRow) * STR + k0 + bCol) * 4);

            #pragma unroll
            for (int mt = 0; mt < 2; mt++) {
                const uint32_t a[4] = { af[mt].x, af[mt].y, af[mt].z, af[mt].w };
                #pragma unroll
                for (int nt = 0; nt < 4; nt++) {
                    const int q = nt >> 1;
                    uint32_t b[2];
                    if (nt & 1) { b[0] = bf[q].z; b[1] = bf[q].w; }
                    else        { b[0] = bf[q].x; b[1] = bf[q].y; }
                    mma_tf32(acc[mt][nt], a, b);
                }
            }
        }

        if (more) {
            #pragma unroll
            for (int q = 0; q < 2; q++) {
                uint4 au = { f2tf32(pa[q].x), f2tf32(pa[q].y), f2tf32(pa[q].z), f2tf32(pa[q].w) };
                *reinterpret_cast<uint4*>(&sA[cur ^ 1][sarow * STR + sacol + q * 4]) = au;
            }
            uint4 bu = { f2tf32(pb.x), f2tf32(pb.y), f2tf32(pb.z), f2tf32(pb.w) };
            *reinterpret_cast<uint4*>(&sB[cur ^ 1][sbrow * STR + sbcol]) = bu;
        }
        __syncthreads();
    }

    // epilogue: raw partials
    float* P = &g_p1[blockIdx.z][0][0];
    #pragma unroll
    for (int mt = 0; mt < 2; mt++) {
        #pragma unroll
        for (int nt = 0; nt < 4; nt++) {
            long row = bm + wm + mt * 16 + (lane >> 2);
            long col = bn + wn + nt * 8 + (lane & 3) * 2;
            *reinterpret_cast<float2*>(&P[row * EE + col]) =
                make_float2(acc[mt][nt][0], acc[mt][nt][1]);
            *reinterpret_cast<float2*>(&P[(row + 8) * EE + col]) =
                make_float2(acc[mt][nt][2], acc[mt][nt][3]);
        }
    }
}

// ---------------- h = relu(sum partials + bias); rowsum -> s ----------------
__global__ void __launch_bounds__(256) h_reduce_kernel(const float* __restrict__ b_emb)
{
    const int row = blockIdx.x;
    const int e = threadIdx.x;
    const int lane = e & 31;
    const int warp = e >> 5;

    float v = b_emb[e];
    #pragma unroll
    for (int ks = 0; ks < KSPLIT; ks++) v += g_p1[ks][row][e];
    v = fmaxf(v, 0.f);
    g_h[(long)row * EE + e] = v;

    float s = v;
    #pragma unroll
    for (int o = 16; o; o >>= 1) s += __shfl_xor_sync(0xffffffffu, s, o);
    __shared__ float red[8];
    if (lane == 0) red[warp] = s;
    __syncthreads();
    if (e == 0) {
        float t = 0.f;
        #pragma unroll
        for (int i = 0; i < 8; i++) t += red[i];
        g_s[row] = t;
    }
}

// ---------------- generic tf32 GEMM (64x64 tile, used for G3) ----------------
#define SMSTRIDE 36

template <bool RELU>
__device__ __forceinline__ void gemm_body(
    const float* __restrict__ A, long lda, long strideA,
    const float* __restrict__ B, long ldb, long strideB,
    float* __restrict__ C, long ldc, long strideC,
    const float* __restrict__ bias, int K)
{
    __shared__ uint32_t sA[2][64 * SMSTRIDE];
    __shared__ uint32_t sB[2][64 * SMSTRIDE];

    const int tid  = threadIdx.x;
    const int lane = tid & 31;
    const int warp = tid >> 5;
    const int wm = (warp >> 1) * 32;
    const int wn = (warp & 1) * 32;
    const long bm = (long)blockIdx.y * 64;
    const long bn = (long)blockIdx.x * 64;

    A += (long)blockIdx.z * strideA;
    B += (long)blockIdx.z * strideB;
    C += (long)blockIdx.z * strideC;

    const int srow = tid >> 3;
    const int scol = (tid & 7) * 4;

    float acc[2][4][4] = {};
    float4 pa[4], pb[4];

    #pragma unroll
    for (int i = 0; i < 4; i++) {
        int r = srow + 16 * i;
        pa[i] = *reinterpret_cast<const float4*>(&A[(bm + r) * lda + 0 + scol]);
        pb[i] = *reinterpret_cast<const float4*>(&B[(bn + r) * ldb + 0 + scol]);
    }
    #pragma unroll
    for (int i = 0; i < 4; i++) {
        int r = srow + 16 * i;
        uint4 au = { f2tf32(pa[i].x), f2tf32(pa[i].y), f2tf32(pa[i].z), f2tf32(pa[i].w) };
        uint4 bu = { f2tf32(pb[i].x), f2tf32(pb[i].y), f2tf32(pb[i].z), f2tf32(pb[i].w) };
        *reinterpret_cast<uint4*>(&sA[0][r * SMSTRIDE + scol]) = au;
        *reinterpret_cast<uint4*>(&sB[0][r * SMSTRIDE + scol]) = bu;
    }
    __syncthreads();

    const int nk = K >> 5;
    for (int kt = 0; kt < nk; kt++) {
        const int cur = kt & 1;
        const bool more = (kt + 1) < nk;

        if (more) {
            int k0 = (kt + 1) << 5;
            #pragma unroll
            for (int i = 0; i < 4; i++) {
                int r = srow + 16 * i;
                pa[i] = *reinterpret_cast<const float4*>(&A[(bm + r) * lda + k0 + scol]);
                pb[i] = *reinterpret_cast<const float4*>(&B[(bn + r) * ldb + k0 + scol]);
            }
        }

        const uint32_t* As = sA[cur];
        const uint32_t* Bs = sB[cur];
        #pragma unroll
        for (int ks = 0; ks < 4; ks++) {
            uint32_t a[2][4], b[4][2];
            const int ar = lane >> 2;
            const int ac = ks * 8 + (lane & 3);
            #pragma unroll
            for (int mt = 0; mt < 2; mt++) {
                int r = wm + mt * 16 + ar;
                a[mt][0] = As[r * SMSTRIDE + ac];
                a[mt][1] = As[(r + 8) * SMSTRIDE + ac];
                a[mt][2] = As[r * SMSTRIDE + ac + 4];
                a[mt][3] = As[(r + 8) * SMSTRIDE + ac + 4];
            }
            #pragma unroll
            for (int nt = 0; nt < 4; nt++) {
                int n = wn + nt * 8 + ar;
                b[nt][0] = Bs[n * SMSTRIDE + ac];
                b[nt][1] = Bs[n * SMSTRIDE + ac + 4];
            }
            #pragma unroll
            for (int mt = 0; mt < 2; mt++)
                #pragma unroll
                for (int nt = 0; nt < 4; nt++)
                    mma_tf32(acc[mt][nt], a[mt], b[nt]);
        }

        if (more) {
            #pragma unroll
            for (int i = 0; i < 4; i++) {
                int r = srow + 16 * i;
                uint4 au = { f2tf32(pa[i].x), f2tf32(pa[i].y), f2tf32(pa[i].z), f2tf32(pa[i].w) };
                uint4 bu = { f2tf32(pb[i].x), f2tf32(pb[i].y), f2tf32(pb[i].z), f2tf32(pb[i].w) };
                *reinterpret_cast<uint4*>(&sA[cur ^ 1][r * SMSTRIDE + scol]) = au;
                *reinterpret_cast<uint4*>(&sB[cur ^ 1][r * SMSTRIDE + scol]) = bu;
            }
        }
        __syncthreads();
    }

    #pragma unroll
    for (int mt = 0; mt < 2; mt++) {
        #pragma unroll
        for (int nt = 0; nt < 4; nt++) {
            long row = bm + wm + mt * 16 + (lane >> 2);
            long col = bn + wn + nt * 8 + (lane & 3) * 2;
            float b0 = bias[col], b1 = bias[col + 1];
            float v0 = acc[mt][nt][0] + b0;
            float v1 = acc[mt][nt][1] + b1;
            float v2 = acc[mt][nt][2] + b0;
            float v3 = acc[mt][nt][3] + b1;
            if (RELU) {
                v0 = fmaxf(v0, 0.f); v1 = fmaxf(v1, 0.f);
                v2 = fmaxf(v2, 0.f); v3 = fmaxf(v3, 0.f);
            }
            *reinterpret_cast<float2*>(&C[row * ldc + col])       = make_float2(v0, v1);
            *reinterpret_cast<float2*>(&C[(row + 8) * ldc + col]) = make_float2(v2, v3);
        }
    }
}

// G3: y[b] = relu(h[b] @ Weff[b]^T + b_red)   grid(4,2,32) x 128
__global__ void __launch_bounds__(128) gemm3_kernel(const float* __restrict__ b_red)
{
    gemm_body<true>(g_h, EE, (long)SS * EE, g_weff, EE, (long)EE * EE,
                    g_y, EE, (long)SS * EE, b_red, EE);
}

// ---------------- G2: Weff[b,e,j] = sum_k s[b,k]*w_red[e, k*E+j] ----------------
__global__ void __launch_bounds__(256) weff_kernel(const float* __restrict__ w_red)
{
    __shared__ float ss[BB * SS];
    int tid = threadIdx.x;
    for (int i = tid; i < BB * SS; i += 256) ss[i] = g_s[i];
    __syncthreads();

    int e = blockIdx.x;
    const float* w = w_red + (long)e * (SS * EE) + tid;
    float acc[BB];
    #pragma unroll
    for (int b = 0; b < BB; b++) acc[b] = 0.f;

    #pragma unroll 8
    for (int k = 0; k < SS; k++) {
        float wv = w[(long)k * EE];
        #pragma unroll
        for (int b = 0; b < BB; b++) acc[b] += ss[b * SS + k] * wv;
    }
    #pragma unroll
    for (int b = 0; b < BB; b++)
        g_weff[(long)b * (EE * EE) + (long)e * EE + tid] = acc[b];
}

// ---------------- G4 split-K ----------------
__global__ void __launch_bounds__(256) red2_partial_kernel(const float* __restrict__ w_red2)
{
    __shared__ float ys[32][68];
    __shared__ float ws[64][65];
    int tid = threadIdx.x;
    int e_base = blockIdx.x * 64;
    long k_base = (long)blockIdx.y * 512;
    int el = tid & 63;
    int bb = (tid >> 6) * 8;
    float acc[8] = {};

    for (int k0 = 0; k0 < 512; k0 += 64) {
        #pragma unroll
        for (int i = 0; i < 2; i++) {
            int idx = tid + i * 256;
            int row = idx >> 4;
            int c4 = (idx & 15) * 4;
            float4 v = *reinterpret_cast<const float4*>(
                &g_y[(long)row * (SS * EE) + k_base + k0 + c4]);
            *reinterpret_cast<float4*>(&ys[row][c4]) = v;
        }
        #pragma unroll
        for (int i = 0; i < 4; i++) {
            int idx = tid + i * 256;
            int row = idx >> 4;
            int c4 = (idx & 15) * 4;
            float4 v = *reinterpret_cast<const float4*>(
                &w_red2[(long)(e_base + row) * (SS * EE) + k_base + k0 + c4]);
            ws[row][c4] = v.x; ws[row][c4 + 1] = v.y;
            ws[row][c4 + 2] = v.z; ws[row][c4 + 3] = v.w;
        }
        __syncthreads();
        #pragma unroll 8
        for (int kk = 0; kk < 64; kk++) {
            float wv = ws[el][kk];
            #pragma unroll
            for (int i = 0; i < 8; i++) acc[i] += ys[bb + i][kk] * wv;
        }
        __syncthreads();
    }
    #pragma unroll
    for (int i = 0; i < 8; i++)
        g_part[(long)blockIdx.y * (BB * EE) + (bb + i) * EE + e_base + el] = acc[i];
}

__global__ void red2_reduce_kernel(const float* __restrict__ b_red2)
{
    int idx = blockIdx.x * 256 + threadIdx.x;
    float s = b_red2[idx & 255];
    #pragma unroll 8
    for (int ks = 0; ks < 64; ks++) s += g_part[(long)ks * (BB * EE) + idx];
    g_y2[idx] = fmaxf(s, 0.f);
}

// ---------------- G5: out = y2 @ w_out^T + b_out ----------------
__global__ void __launch_bounds__(256) out_kernel(
    const float* __restrict__ w_out, const float* __restrict__ b_out,
    float* __restrict__ out)
{
    __shared__ float ys[32][68];
    __shared__ float ws[64][65];
    int tid = threadIdx.x;
    int v_base = blockIdx.x * 64;
    int vl = tid & 63;
    int bb = (tid >> 6) * 8;
    float acc[8] = {};

    for (int k0 = 0; k0 < EE; k0 += 64) {
        #pragma unroll
        for (int i = 0; i < 2; i++) {
            int idx = tid + i * 256;
            int row = idx >> 4;
            int c4 = (idx & 15) * 4;
            float4 v = *reinterpret_cast<const float4*>(&g_y2[row * EE + k0 + c4]);
            *reinterpret_cast<float4*>(&ys[row][c4]) = v;
        }
        #pragma unroll
        for (int i = 0; i < 4; i++) {
            int idx = tid + i * 256;
            int row = idx >> 4;
            int c4 = (idx & 15) * 4;
            float4 v = *reinterpret_cast<const float4*>(
                &w_out[(long)(v_base + row) * EE + k0 + c4]);
            ws[row][c4] = v.x; ws[row][c4 + 1] = v.y;
            ws[row][c4 + 2] = v.z; ws[row][c4 + 3] = v.w;
        }
        __syncthreads();
        #pragma unroll 8
        for (int kk = 0; kk < 64; kk++) {
            float wv = ws[vl][kk];
            #pragma unroll
            for (int i = 0; i < 8; i++) acc[i] += ys[bb + i][kk] * wv;
        }
        __syncthreads();
    }
    float bo = b_out[v_base + vl];
    #pragma unroll
    for (int i = 0; i < 8; i++)
        out[(long)(bb + i) * VV + v_base + vl] = acc[i] + bo;
}

// ---------------- launch ----------------
extern "C" void kernel_launch(void* const* d_in, const int* in_sizes, int n_in,
                              void* d_out, int out_size)
{
    const float* x      = (const float*)d_in[0];
    const float* w_emb  = (const float*)d_in[1];
    const float* b_emb  = (const float*)d_in[2];
    const float* w_red  = (const float*)d_in[3];
    const float* b_red  = (const float*)d_in[4];
    const float* w_red2 = (const float*)d_in[5];
    const float* b_red2 = (const float*)d_in[6];
    const float* w_out  = (const float*)d_in[7];
    const float* b_out  = (const float*)d_in[8];
    float* out = (float*)d_out;

    dummy_kernel<<<1, 32>>>();                              // shift ncu slot
    dummy_kernel<<<1, 32>>>();                              // so the profiled
    dummy_kernel<<<1, 32>>>();                              // launch is g1
    g1_kernel<<<dim3(4, 32, KSPLIT), 256>>>(x, w_emb);      // G1 partials
    h_reduce_kernel<<<MR, 256>>>(b_emb);                    // h + rowsum
    weff_kernel<<<256, 256>>>(w_red);                       // Weff
    gemm3_kernel<<<dim3(4, 2, 32), 128>>>(b_red);           // y
    red2_partial_kernel<<<dim3(4, 64), 256>>>(w_red2);      // G4 partials
    red2_reduce_kernel<<<32, 256>>>(b_red2);                // y2
    out_kernel<<<128, 256>>>(w_out, b_out, out);            // out
}

// round 8
// speedup vs baseline: 1.0419x; 1.0419x over previous
#include <cuda_runtime.h>
#include <cstdint>

// Shapes (fixed by the problem)
#define BB   32
#define SS   128
#define VV   8192
#define EE   256
#define MR   (BB*SS)

// G1 split-K config
#define KSPLIT 8
#define KCHUNK (VV/KSPLIT)   // 1024
#define STR    20            // smem row stride in uint32 (16 + 4 pad)

// ---------------- scratch (device globals; no allocation) ----------------
__device__ float g_p1[KSPLIT][MR][EE];  // G1 split-K partials 32 MB
__device__ float g_h[MR*EE];            // h     [4096,256]
__device__ float g_s[MR];               // rowsum(h)
__device__ float g_weff[BB*EE*EE];      // Weff  [32,256,256]
__device__ float g_y[MR*EE];            // y     [4096,256]
__device__ float g_part[64*BB*EE];      // G4 split-K partials
__device__ float g_y2[BB*EE];           // y2    [32,256]

// ---------------- helpers ----------------
__device__ __forceinline__ uint32_t f2tf32(float f) {
    uint32_t u;
    asm("cvt.rna.tf32.f32 %0, %1;" : "=r"(u) : "f"(f));
    return u;
}

__device__ __forceinline__ uint32_t smem_u32(const void* p) {
    uint32_t a;
    asm("{ .reg .u64 t; cvta.to.shared.u64 t, %1; cvt.u32.u64 %0, t; }" : "=r"(a) : "l"(p));
    return a;
}

__device__ __forceinline__ uint4 ldsm_x4(uint32_t addr) {
    uint4 r;
    asm volatile("ldmatrix.sync.aligned.m8n8.x4.shared.b16 {%0,%1,%2,%3}, [%4];"
        : "=r"(r.x), "=r"(r.y), "=r"(r.z), "=r"(r.w) : "r"(addr));
    return r;
}

__device__ __forceinline__ void mma_tf32(float c[4], const uint4 a, const uint32_t b0, const uint32_t b1) {
    asm volatile(
        "mma.sync.aligned.m16n8k8.row.col.f32.tf32.tf32.f32 "
        "{%0,%1,%2,%3}, {%4,%5,%6,%7}, {%8,%9}, {%0,%1,%2,%3};"
        : "+f"(c[0]), "+f"(c[1]), "+f"(c[2]), "+f"(c[3])
        : "r"(a.x), "r"(a.y), "r"(a.z), "r"(a.w), "r"(b0), "r"(b1));
}

// profile-slot shifter (3 launches before g1 so ncu's fixed skip lands on g1)
__global__ void dummy_kernel() {}

// ===================================================================
// G1 split-K: partial[kz] = x[:, kz*1024:+1024] @ w_emb^T chunk
// CTA tile 128m x 128n x 16k, 128 threads = 4 warps (2m x 2n),
// warp tile 64x64 (acc = 128 regs). L1 traffic ~0.24 B/MAC -> tensor-bound.
// grid (2=n, 32=m, 8=kz) = 512 CTAs, 2 CTAs/SM.
// ===================================================================
__global__ void __launch_bounds__(128) g1_kernel(
    const float* __restrict__ x, const float* __restrict__ w_emb)
{
    __shared__ uint32_t sA[2][128 * STR];   // 10 KB x2
    __shared__ uint32_t sB[2][128 * STR];   // 10 KB x2

    const int tid  = threadIdx.x;
    const int lane = tid & 31;
    const int warp = tid >> 5;
    const int wm = (warp >> 1) * 64;        // 0,64
    const int wn = (warp & 1) * 64;         // 0,64
    const long bm = (long)blockIdx.y * 128;
    const long bn = (long)blockIdx.x * 128;
    const long kbase = (long)blockIdx.z * KCHUNK;

    // staging: each thread owns one row of A and one row of B (16 floats each)
    const float* Arow = x + (bm + tid) * VV + kbase;
    const float* Brow = w_emb + (bn + tid) * VV + kbase;

    const uint32_t sAb[2] = { smem_u32(&sA[0][0]), smem_u32(&sA[1][0]) };
    const uint32_t sBb[2] = { smem_u32(&sB[0][0]), smem_u32(&sB[1][0]) };

    // ldmatrix per-lane row/col offsets (mapping validated in R5)
    const int aRow = ((lane >> 3) & 1) * 8 + (lane & 7);
    const int aCol = (lane >> 4) * 4;
    const int bRow = ((lane >> 4) & 1) * 8 + (lane & 7);
    const int bCol = ((lane >> 3) & 1) * 4;

    float acc[4][8][4] = {};
    float4 pa[4], pb[4];

    // prefetch + stage tile 0
    #pragma unroll
    for (int q = 0; q < 4; q++) {
        pa[q] = *reinterpret_cast<const float4*>(Arow + q * 4);
        pb[q] = *reinterpret_cast<const float4*>(Brow + q * 4);
    }
    #pragma unroll
    for (int q = 0; q < 4; q++) {
        uint4 au = { f2tf32(pa[q].x), f2tf32(pa[q].y), f2tf32(pa[q].z), f2tf32(pa[q].w) };
        uint4 bu = { f2tf32(pb[q].x), f2tf32(pb[q].y), f2tf32(pb[q].z), f2tf32(pb[q].w) };
        *reinterpret_cast<uint4*>(&sA[0][tid * STR + q * 4]) = au;
        *reinterpret_cast<uint4*>(&sB[0][tid * STR + q * 4]) = bu;
    }
    __syncthreads();

    const int nkt = KCHUNK / 16;            // 64
    for (int kt = 0; kt < nkt; kt++) {
        const int cur = kt & 1;
        const bool more = (kt + 1) < nkt;

        if (more) {
            const float* Ap = Arow + (kt + 1) * 16;
            const float* Bp = Brow + (kt + 1) * 16;
            #pragma unroll
            for (int q = 0; q < 4; q++) {
                pa[q] = *reinterpret_cast<const float4*>(Ap + q * 4);
                pb[q] = *reinterpret_cast<const float4*>(Bp + q * 4);
            }
        }

        const uint32_t ab = sAb[cur];
        const uint32_t bb = sBb[cur];
        #pragma unroll
        for (int ks = 0; ks < 2; ks++) {
            const int k0 = ks * 8;
            uint4 af[4], bf[4];
            #pragma unroll
            for (int mi = 0; mi < 4; mi++)
                af[mi] = ldsm_x4(ab + ((wm + mi * 16 + aRow) * STR + k0 + aCol) * 4);
            #pragma unroll
            for (int q = 0; q < 4; q++)
                bf[q] = ldsm_x4(bb + ((wn + q * 16 + bRow) * STR + k0 + bCol) * 4);

            #pragma unroll
            for (int mi = 0; mi < 4; mi++) {
                #pragma unroll
                for (int nt = 0; nt < 8; nt++) {
                    const int q = nt >> 1;
                    if (nt & 1) mma_tf32(acc[mi][nt], af[mi], bf[q].z, bf[q].w);
                    else        mma_tf32(acc[mi][nt], af[mi], bf[q].x, bf[q].y);
                }
            }
        }

        if (more) {
            #pragma unroll
            for (int q = 0; q < 4; q++) {
                uint4 au = { f2tf32(pa[q].x), f2tf32(pa[q].y), f2tf32(pa[q].z), f2tf32(pa[q].w) };
                uint4 bu = { f2tf32(pb[q].x), f2tf32(pb[q].y), f2tf32(pb[q].z), f2tf32(pb[q].w) };
                *reinterpret_cast<uint4*>(&sA[cur ^ 1][tid * STR + q * 4]) = au;
                *reinterpret_cast<uint4*>(&sB[cur ^ 1][tid * STR + q * 4]) = bu;
            }
        }
        __syncthreads();
    }

    // epilogue: raw partials
    float* P = &g_p1[blockIdx.z][0][0];
    #pragma unroll
    for (int mi = 0; mi < 4; mi++) {
        #pragma unroll
        for (int nt = 0; nt < 8; nt++) {
            long row = bm + wm + mi * 16 + (lane >> 2);
            long col = bn + wn + nt * 8 + (lane & 3) * 2;
            *reinterpret_cast<float2*>(&P[row * EE + col]) =
                make_float2(acc[mi][nt][0], acc[mi][nt][1]);
            *reinterpret_cast<float2*>(&P[(row + 8) * EE + col]) =
                make_float2(acc[mi][nt][2], acc[mi][nt][3]);
        }
    }
}

// ---------------- h = relu(sum partials + bias); rowsum -> s ----------------
__global__ void __launch_bounds__(256) h_reduce_kernel(const float* __restrict__ b_emb)
{
    const int row = blockIdx.x;
    const int e = threadIdx.x;
    const int lane = e & 31;
    const int warp = e >> 5;

    float v = b_emb[e];
    #pragma unroll
    for (int ks = 0; ks < KSPLIT; ks++) v += g_p1[ks][row][e];
    v = fmaxf(v, 0.f);
    g_h[(long)row * EE + e] = v;

    float s = v;
    #pragma unroll
    for (int o = 16; o; o >>= 1) s += __shfl_xor_sync(0xffffffffu, s, o);
    __shared__ float red[8];
    if (lane == 0) red[warp] = s;
    __syncthreads();
    if (e == 0) {
        float t = 0.f;
        #pragma unroll
        for (int i = 0; i < 8; i++) t += red[i];
        g_s[row] = t;
    }
}

// ---------------- generic tf32 GEMM (64x64 tile, used for G3) ----------------
#define SMSTRIDE 36

__device__ __forceinline__ void mma_tf32_arr(float c[4], const uint32_t a[4], const uint32_t b[2]) {
    asm volatile(
        "mma.sync.aligned.m16n8k8.row.col.f32.tf32.tf32.f32 "
        "{%0,%1,%2,%3}, {%4,%5,%6,%7}, {%8,%9}, {%0,%1,%2,%3};"
        : "+f"(c[0]), "+f"(c[1]), "+f"(c[2]), "+f"(c[3])
        : "r"(a[0]), "r"(a[1]), "r"(a[2]), "r"(a[3]), "r"(b[0]), "r"(b[1]));
}

template <bool RELU>
__device__ __forceinline__ void gemm_body(
    const float* __restrict__ A, long lda, long strideA,
    const float* __restrict__ B, long ldb, long strideB,
    float* __restrict__ C, long ldc, long strideC,
    const float* __restrict__ bias, int K)
{
    __shared__ uint32_t sA[2][64 * SMSTRIDE];
    __shared__ uint32_t sB[2][64 * SMSTRIDE];

    const int tid  = threadIdx.x;
    const int lane = tid & 31;
    const int warp = tid >> 5;
    const int wm = (warp >> 1) * 32;
    const int wn = (warp & 1) * 32;
    const long bm = (long)blockIdx.y * 64;
    const long bn = (long)blockIdx.x * 64;

    A += (long)blockIdx.z * strideA;
    B += (long)blockIdx.z * strideB;
    C += (long)blockIdx.z * strideC;

    const int srow = tid >> 3;
    const int scol = (tid & 7) * 4;

    float acc[2][4][4] = {};
    float4 pa[4], pb[4];

    #pragma unroll
    for (int i = 0; i < 4; i++) {
        int r = srow + 16 * i;
        pa[i] = *reinterpret_cast<const float4*>(&A[(bm + r) * lda + 0 + scol]);
        pb[i] = *reinterpret_cast<const float4*>(&B[(bn + r) * ldb + 0 + scol]);
    }
    #pragma unroll
    for (int i = 0; i < 4; i++) {
        int r = srow + 16 * i;
        uint4 au = { f2tf32(pa[i].x), f2tf32(pa[i].y), f2tf32(pa[i].z), f2tf32(pa[i].w) };
        uint4 bu = { f2tf32(pb[i].x), f2tf32(pb[i].y), f2tf32(pb[i].z), f2tf32(pb[i].w) };
        *reinterpret_cast<uint4*>(&sA[0][r * SMSTRIDE + scol]) = au;
        *reinterpret_cast<uint4*>(&sB[0][r * SMSTRIDE + scol]) = bu;
    }
    __syncthreads();

    const int nk = K >> 5;
    for (int kt = 0; kt < nk; kt++) {
        const int cur = kt & 1;
        const bool more = (kt + 1) < nk;

        if (more) {
            int k0 = (kt + 1) << 5;
            #pragma unroll
            for (int i = 0; i < 4; i++) {
                int r = srow + 16 * i;
                pa[i] = *reinterpret_cast<const float4*>(&A[(bm + r) * lda + k0 + scol]);
                pb[i] = *reinterpret_cast<const float4*>(&B[(bn + r) * ldb + k0 + scol]);
            }
        }

        const uint32_t* As = sA[cur];
        const uint32_t* Bs = sB[cur];
        #pragma unroll
        for (int ks = 0; ks < 4; ks++) {
            uint32_t a[2][4], b[4][2];
            const int ar = lane >> 2;
            const int ac = ks * 8 + (lane & 3);
            #pragma unroll
            for (int mt = 0; mt < 2; mt++) {
                int r = wm + mt * 16 + ar;
                a[mt][0] = As[r * SMSTRIDE + ac];
                a[mt][1] = As[(r + 8) * SMSTRIDE + ac];
                a[mt][2] = As[r * SMSTRIDE + ac + 4];
                a[mt][3] = As[(r + 8) * SMSTRIDE + ac + 4];
            }
            #pragma unroll
            for (int nt = 0; nt < 4; nt++) {
                int n = wn + nt * 8 + ar;
                b[nt][0] = Bs[n * SMSTRIDE + ac];
                b[nt][1] = Bs[n * SMSTRIDE + ac + 4];
            }
            #pragma unroll
            for (int mt = 0; mt < 2; mt++)
                #pragma unroll
                for (int nt = 0; nt < 4; nt++)
                    mma_tf32_arr(acc[mt][nt], a[mt], b[nt]);
        }

        if (more) {
            #pragma unroll
            for (int i = 0; i < 4; i++) {
                int r = srow + 16 * i;
                uint4 au = { f2tf32(pa[i].x), f2tf32(pa[i].y), f2tf32(pa[i].z), f2tf32(pa[i].w) };
                uint4 bu = { f2tf32(pb[i].x), f2tf32(pb[i].y), f2tf32(pb[i].z), f2tf32(pb[i].w) };
                *reinterpret_cast<uint4*>(&sA[cur ^ 1][r * SMSTRIDE + scol]) = au;
                *reinterpret_cast<uint4*>(&sB[cur ^ 1][r * SMSTRIDE + scol]) = bu;
            }
        }
        __syncthreads();
    }

    #pragma unroll
    for (int mt = 0; mt < 2; mt++) {
        #pragma unroll
        for (int nt = 0; nt < 4; nt++) {
            long row = bm + wm + mt * 16 + (lane >> 2);
            long col = bn + wn + nt * 8 + (lane & 3) * 2;
            float b0 = bias[col], b1 = bias[col + 1];
            float v0 = acc[mt][nt][0] + b0;
            float v1 = acc[mt][nt][1] + b1;
            float v2 = acc[mt][nt][2] + b0;
            float v3 = acc[mt][nt][3] + b1;
            if (RELU) {
                v0 = fmaxf(v0, 0.f); v1 = fmaxf(v1, 0.f);
                v2 = fmaxf(v2, 0.f); v3 = fmaxf(v3, 0.f);
            }
            *reinterpret_cast<float2*>(&C[row * ldc + col])       = make_float2(v0, v1);
            *reinterpret_cast<float2*>(&C[(row + 8) * ldc + col]) = make_float2(v2, v3);
        }
    }
}

// G3: y[b] = relu(h[b] @ Weff[b]^T + b_red)   grid(4,2,32) x 128
__global__ void __launch_bounds__(128) gemm3_kernel(const float* __restrict__ b_red)
{
    gemm_body<true>(g_h, EE, (long)SS * EE, g_weff, EE, (long)EE * EE,
                    g_y, EE, (long)SS * EE, b_red, EE);
}

// ---------------- G2: Weff[b,e,j] = sum_k s[b,k]*w_red[e, k*E+j] ----------------
__global__ void __launch_bounds__(256) weff_kernel(const float* __restrict__ w_red)
{
    __shared__ float ss[BB * SS];
    int tid = threadIdx.x;
    for (int i = tid; i < BB * SS; i += 256) ss[i] = g_s[i];
    __syncthreads();

    int e = blockIdx.x;
    const float* w = w_red + (long)e * (SS * EE) + tid;
    float acc[BB];
    #pragma unroll
    for (int b = 0; b < BB; b++) acc[b] = 0.f;

    #pragma unroll 8
    for (int k = 0; k < SS; k++) {
        float wv = w[(long)k * EE];
        #pragma unroll
        for (int b = 0; b < BB; b++) acc[b] += ss[b * SS + k] * wv;
    }
    #pragma unroll
    for (int b = 0; b < BB; b++)
        g_weff[(long)b * (EE * EE) + (long)e * EE + tid] = acc[b];
}

// ---------------- G4 split-K ----------------
__global__ void __launch_bounds__(256) red2_partial_kernel(const float* __restrict__ w_red2)
{
    __shared__ float ys[32][68];
    __shared__ float ws[64][65];
    int tid = threadIdx.x;
    int e_base = blockIdx.x * 64;
    long k_base = (long)blockIdx.y * 512;
    int el = tid & 63;
    int bb = (tid >> 6) * 8;
    float acc[8] = {};

    for (int k0 = 0; k0 < 512; k0 += 64) {
        #pragma unroll
        for (int i = 0; i < 2; i++) {
            int idx = tid + i * 256;
            int row = idx >> 4;
            int c4 = (idx & 15) * 4;
            float4 v = *reinterpret_cast<const float4*>(
                &g_y[(long)row * (SS * EE) + k_base + k0 + c4]);
            *reinterpret_cast<float4*>(&ys[row][c4]) = v;
        }
        #pragma unroll
        for (int i = 0; i < 4; i++) {
            int idx = tid + i * 256;
            int row = idx >> 4;
            int c4 = (idx & 15) * 4;
            float4 v = *reinterpret_cast<const float4*>(
                &w_red2[(long)(e_base + row) * (SS * EE) + k_base + k0 + c4]);
            ws[row][c4] = v.x; ws[row][c4 + 1] = v.y;
            ws[row][c4 + 2] = v.z; ws[row][c4 + 3] = v.w;
        }
        __syncthreads();
        #pragma unroll 8
        for (int kk = 0; kk < 64; kk++) {
            float wv = ws[el][kk];
            #pragma unroll
            for (int i = 0; i < 8; i++) acc[i] += ys[bb + i][kk] * wv;
        }
        __syncthreads();
    }
    #pragma unroll
    for (int i = 0; i < 8; i++)
        g_part[(long)blockIdx.y * (BB * EE) + (bb + i) * EE + e_base + el] = acc[i];
}

__global__ void red2_reduce_kernel(const float* __restrict__ b_red2)
{
    int idx = blockIdx.x * 256 + threadIdx.x;
    float s = b_red2[idx & 255];
    #pragma unroll 8
    for (int ks = 0; ks < 64; ks++) s += g_part[(long)ks * (BB * EE) + idx];
    g_y2[idx] = fmaxf(s, 0.f);
}

// ---------------- G5: out = y2 @ w_out^T + b_out ----------------
__global__ void __launch_bounds__(256) out_kernel(
    const float* __restrict__ w_out, const float* __restrict__ b_out,
    float* __restrict__ out)
{
    __shared__ float ys[32][68];
    __shared__ float ws[64][65];
    int tid = threadIdx.x;
    int v_base = blockIdx.x * 64;
    int vl = tid & 63;
    int bb = (tid >> 6) * 8;
    float acc[8] = {};

    for (int k0 = 0; k0 < EE; k0 += 64) {
        #pragma unroll
        for (int i = 0; i < 2; i++) {
            int idx = tid + i * 256;
            int row = idx >> 4;
            int c4 = (idx & 15) * 4;
            float4 v = *reinterpret_cast<const float4*>(&g_y2[row * EE + k0 + c4]);
            *reinterpret_cast<float4*>(&ys[row][c4]) = v;
        }
        #pragma unroll
        for (int i = 0; i < 4; i++) {
            int idx = tid + i * 256;
            int row = idx >> 4;
            int c4 = (idx & 15) * 4;
            float4 v = *reinterpret_cast<const float4*>(
                &w_out[(long)(v_base + row) * EE + k0 + c4]);
            ws[row][c4] = v.x; ws[row][c4 + 1] = v.y;
            ws[row][c4 + 2] = v.z; ws[row][c4 + 3] = v.w;
        }
        __syncthreads();
        #pragma unroll 8
        for (int kk = 0; kk < 64; kk++) {
            float wv = ws[vl][kk];
            #pragma unroll
            for (int i = 0; i < 8; i++) acc[i] += ys[bb + i][kk] * wv;
        }
        __syncthreads();
    }
    float bo = b_out[v_base + vl];
    #pragma unroll
    for (int i = 0; i < 8; i++)
        out[(long)(bb + i) * VV + v_base + vl] = acc[i] + bo;
}

// ---------------- launch ----------------
extern "C" void kernel_launch(void* const* d_in, const int* in_sizes, int n_in,
                              void* d_out, int out_size)
{
    const float* x      = (const float*)d_in[0];
    const float* w_emb  = (const float*)d_in[1];
    const float* b_emb  = (const float*)d_in[2];
    const float* w_red  = (const float*)d_in[3];
    const float* b_red  = (const float*)d_in[4];
    const float* w_red2 = (const float*)d_in[5];
    const float* b_red2 = (const float*)d_in[6];
    const float* w_out  = (const float*)d_in[7];
    const float* b_out  = (const float*)d_in[8];
    float* out = (float*)d_out;

    dummy_kernel<<<1, 32>>>();                              // shift ncu slot
    dummy_kernel<<<1, 32>>>();                              // so the profiled
    dummy_kernel<<<1, 32>>>();                              // launch is g1
    g1_kernel<<<dim3(2, 32, KSPLIT), 128>>>(x, w_emb);      // G1 partials
    h_reduce_kernel<<<MR, 256>>>(b_emb);                    // h + rowsum
    weff_kernel<<<256, 256>>>(w_red);                       // Weff
    gemm3_kernel<<<dim3(4, 2, 32), 128>>>(b_red);           // y
    red2_partial_kernel<<<dim3(4, 64), 256>>>(w_red2);      // G4 partials
    red2_reduce_kernel<<<32, 256>>>(b_red2);                // y2
    out_kernel<<<128, 256>>>(w_out, b_out, out);            // out
}

// round 9
// speedup vs baseline: 1.2736x; 1.2225x over previous
#include <cuda_runtime.h>
#include <cstdint>

// Shapes (fixed by the problem)
#define BB   32
#define SS   128
#define VV   8192
#define EE   256
#define MR   (BB*SS)

// G1 split-K config
#define KSPLIT 8
#define KCHUNK (VV/KSPLIT)   // 1024
#define STR    20            // smem row stride in uint32 (16 + 4 pad)

// ---------------- scratch (device globals; no allocation) ----------------
__device__ float g_p1[KSPLIT][MR][EE];  // G1 split-K partials 32 MB
__device__ float g_h[MR*EE];            // h     [4096,256]
__device__ float g_s[MR];               // rowsum(h)
__device__ float g_weff[BB*EE*EE];      // Weff  [32,256,256]
__device__ float g_y[MR*EE];            // y     [4096,256]
__device__ float g_part[64*BB*EE];      // G4 split-K partials
__device__ float g_y2[BB*EE];           // y2    [32,256]

// ---------------- helpers ----------------
__device__ __forceinline__ uint32_t f2tf32(float f) {
    uint32_t u;
    asm("cvt.rna.tf32.f32 %0, %1;" : "=r"(u) : "f"(f));
    return u;
}

__device__ __forceinline__ uint32_t smem_u32(const void* p) {
    uint32_t a;
    asm("{ .reg .u64 t; cvta.to.shared.u64 t, %1; cvt.u32.u64 %0, t; }" : "=r"(a) : "l"(p));
    return a;
}

__device__ __forceinline__ uint4 ldsm_x4(uint32_t addr) {
    uint4 r;
    asm volatile("ldmatrix.sync.aligned.m8n8.x4.shared.b16 {%0,%1,%2,%3}, [%4];"
        : "=r"(r.x), "=r"(r.y), "=r"(r.z), "=r"(r.w) : "r"(addr));
    return r;
}

__device__ __forceinline__ void mma_tf32(float c[4], const uint4 a, const uint32_t b0, const uint32_t b1) {
    asm volatile(
        "mma.sync.aligned.m16n8k8.row.col.f32.tf32.tf32.f32 "
        "{%0,%1,%2,%3}, {%4,%5,%6,%7}, {%8,%9}, {%0,%1,%2,%3};"
        : "+f"(c[0]), "+f"(c[1]), "+f"(c[2]), "+f"(c[3])
        : "r"(a.x), "r"(a.y), "r"(a.z), "r"(a.w), "r"(b0), "r"(b1));
}

// profile-slot shifter (3 launches before g1 so ncu's fixed skip lands on g1)
__global__ void dummy_kernel() {}

// ===================================================================
// G1 split-K: partial[kz] = x[:, kz*1024:+1024] @ w_emb^T chunk
// CTA tile 128m x 128n x 16k, 128 threads = 4 warps (2m x 2n),
// warp tile 64x64. COALESCED staging: 4 lanes per row (8 lines/instr
// instead of 32) -> LDG wavefronts per k-tile drop 1024 -> 256.
// grid (2=n, 32=m, 8=kz) = 512 CTAs, 2 CTAs/SM.
// ===================================================================
__global__ void __launch_bounds__(128) g1_kernel(
    const float* __restrict__ x, const float* __restrict__ w_emb)
{
    __shared__ uint32_t sA[2][128 * STR];   // 10 KB x2
    __shared__ uint32_t sB[2][128 * STR];   // 10 KB x2

    const int tid  = threadIdx.x;
    const int lane = tid & 31;
    const int warp = tid >> 5;
    const int wm = (warp >> 1) * 64;        // 0,64
    const int wn = (warp & 1) * 64;         // 0,64
    const long bm = (long)blockIdx.y * 128;
    const long bn = (long)blockIdx.x * 128;
    const long kbase = (long)blockIdx.z * KCHUNK;

    // coalesced staging: 4 lanes per row, rows srow4 + 32*i (i=0..3)
    const int srow4 = tid >> 2;             // 0..31
    const int sc4   = (tid & 3) * 4;        // float offset within row: 0,4,8,12
    const float* Abase = x + (bm + srow4) * VV + kbase + sc4;
    const float* Bbase = w_emb + (bn + srow4) * VV + kbase + sc4;
    const long rowstep = 32L * VV;          // +32 rows

    const uint32_t sAb[2] = { smem_u32(&sA[0][0]), smem_u32(&sA[1][0]) };
    const uint32_t sBb[2] = { smem_u32(&sB[0][0]), smem_u32(&sB[1][0]) };

    // ldmatrix per-lane row/col offsets (mapping validated in R5)
    const int aRow = ((lane >> 3) & 1) * 8 + (lane & 7);
    const int aCol = (lane >> 4) * 4;
    const int bRow = ((lane >> 4) & 1) * 8 + (lane & 7);
    const int bCol = ((lane >> 3) & 1) * 4;

    float acc[4][8][4] = {};
    float4 pa[4], pb[4];

    // prefetch + stage tile 0
    #pragma unroll
    for (int i = 0; i < 4; i++) {
        pa[i] = *reinterpret_cast<const float4*>(Abase + i * rowstep);
        pb[i] = *reinterpret_cast<const float4*>(Bbase + i * rowstep);
    }
    #pragma unroll
    for (int i = 0; i < 4; i++) {
        uint4 au = { f2tf32(pa[i].x), f2tf32(pa[i].y), f2tf32(pa[i].z), f2tf32(pa[i].w) };
        uint4 bu = { f2tf32(pb[i].x), f2tf32(pb[i].y), f2tf32(pb[i].z), f2tf32(pb[i].w) };
        *reinterpret_cast<uint4*>(&sA[0][(srow4 + 32 * i) * STR + sc4]) = au;
        *reinterpret_cast<uint4*>(&sB[0][(srow4 + 32 * i) * STR + sc4]) = bu;
    }
    __syncthreads();

    const int nkt = KCHUNK / 16;            // 64
    for (int kt = 0; kt < nkt; kt++) {
        const int cur = kt & 1;
        const bool more = (kt + 1) < nkt;

        if (more) {
            const float* Ap = Abase + (kt + 1) * 16;
            const float* Bp = Bbase + (kt + 1) * 16;
            #pragma unroll
            for (int i = 0; i < 4; i++) {
                pa[i] = *reinterpret_cast<const float4*>(Ap + i * rowstep);
                pb[i] = *reinterpret_cast<const float4*>(Bp + i * rowstep);
            }
        }

        const uint32_t ab = sAb[cur];
        const uint32_t bb = sBb[cur];
        #pragma unroll
        for (int ks = 0; ks < 2; ks++) {
            const int k0 = ks * 8;
            uint4 af[4], bf[4];
            #pragma unroll
            for (int mi = 0; mi < 4; mi++)
                af[mi] = ldsm_x4(ab + ((wm + mi * 16 + aRow) * STR + k0 + aCol) * 4);
            #pragma unroll
            for (int q = 0; q < 4; q++)
                bf[q] = ldsm_x4(bb + ((wn + q * 16 + bRow) * STR + k0 + bCol) * 4);

            #pragma unroll
            for (int mi = 0; mi < 4; mi++) {
                #pragma unroll
                for (int nt = 0; nt < 8; nt++) {
                    const int q = nt >> 1;
                    if (nt & 1) mma_tf32(acc[mi][nt], af[mi], bf[q].z, bf[q].w);
                    else        mma_tf32(acc[mi][nt], af[mi], bf[q].x, bf[q].y);
                }
            }
        }

        if (more) {
            #pragma unroll
            for (int i = 0; i < 4; i++) {
                uint4 au = { f2tf32(pa[i].x), f2tf32(pa[i].y), f2tf32(pa[i].z), f2tf32(pa[i].w) };
                uint4 bu = { f2tf32(pb[i].x), f2tf32(pb[i].y), f2tf32(pb[i].z), f2tf32(pb[i].w) };
                *reinterpret_cast<uint4*>(&sA[cur ^ 1][(srow4 + 32 * i) * STR + sc4]) = au;
                *reinterpret_cast<uint4*>(&sB[cur ^ 1][(srow4 + 32 * i) * STR + sc4]) = bu;
            }
        }
        __syncthreads();
    }

    // epilogue: raw partials
    float* P = &g_p1[blockIdx.z][0][0];
    #pragma unroll
    for (int mi = 0; mi < 4; mi++) {
        #pragma unroll
        for (int nt = 0; nt < 8; nt++) {
            long row = bm + wm + mi * 16 + (lane >> 2);
            long col = bn + wn + nt * 8 + (lane & 3) * 2;
            *reinterpret_cast<float2*>(&P[row * EE + col]) =
                make_float2(acc[mi][nt][0], acc[mi][nt][1]);
            *reinterpret_cast<float2*>(&P[(row + 8) * EE + col]) =
                make_float2(acc[mi][nt][2], acc[mi][nt][3]);
        }
    }
}

// ---------------- h = relu(sum partials + bias); rowsum -> s ----------------
__global__ void __launch_bounds__(256) h_reduce_kernel(const float* __restrict__ b_emb)
{
    const int row = blockIdx.x;
    const int e = threadIdx.x;
    const int lane = e & 31;
    const int warp = e >> 5;

    float v = b_emb[e];
    #pragma unroll
    for (int ks = 0; ks < KSPLIT; ks++) v += g_p1[ks][row][e];
    v = fmaxf(v, 0.f);
    g_h[(long)row * EE + e] = v;

    float s = v;
    #pragma unroll
    for (int o = 16; o; o >>= 1) s += __shfl_xor_sync(0xffffffffu, s, o);
    __shared__ float red[8];
    if (lane == 0) red[warp] = s;
    __syncthreads();
    if (e == 0) {
        float t = 0.f;
        #pragma unroll
        for (int i = 0; i < 8; i++) t += red[i];
        g_s[row] = t;
    }
}

// ---------------- generic tf32 GEMM (64x64 tile, used for G3) ----------------
#define SMSTRIDE 36

__device__ __forceinline__ void mma_tf32_arr(float c[4], const uint32_t a[4], const uint32_t b[2]) {
    asm volatile(
        "mma.sync.aligned.m16n8k8.row.col.f32.tf32.tf32.f32 "
        "{%0,%1,%2,%3}, {%4,%5,%6,%7}, {%8,%9}, {%0,%1,%2,%3};"
        : "+f"(c[0]), "+f"(c[1]), "+f"(c[2]), "+f"(c[3])
        : "r"(a[0]), "r"(a[1]), "r"(a[2]), "r"(a[3]), "r"(b[0]), "r"(b[1]));
}

template <bool RELU>
__device__ __forceinline__ void gemm_body(
    const float* __restrict__ A, long lda, long strideA,
    const float* __restrict__ B, long ldb, long strideB,
    float* __restrict__ C, long ldc, long strideC,
    const float* __restrict__ bias, int K)
{
    __shared__ uint32_t sA[2][64 * SMSTRIDE];
    __shared__ uint32_t sB[2][64 * SMSTRIDE];

    const int tid  = threadIdx.x;
    const int lane = tid & 31;
    const int warp = tid >> 5;
    const int wm = (warp >> 1) * 32;
    const int wn = (warp & 1) * 32;
    const long bm = (long)blockIdx.y * 64;
    const long bn = (long)blockIdx.x * 64;

    A += (long)blockIdx.z * strideA;
    B += (long)blockIdx.z * strideB;
    C += (long)blockIdx.z * strideC;

    const int srow = tid >> 3;
    const int scol = (tid & 7) * 4;

    float acc[2][4][4] = {};
    float4 pa[4], pb[4];

    #pragma unroll
    for (int i = 0; i < 4; i++) {
        int r = srow + 16 * i;
        pa[i] = *reinterpret_cast<const float4*>(&A[(bm + r) * lda + 0 + scol]);
        pb[i] = *reinterpret_cast<const float4*>(&B[(bn + r) * ldb + 0 + scol]);
    }
    #pragma unroll
    for (int i = 0; i < 4; i++) {
        int r = srow + 16 * i;
        uint4 au = { f2tf32(pa[i].x), f2tf32(pa[i].y), f2tf32(pa[i].z), f2tf32(pa[i].w) };
        uint4 bu = { f2tf32(pb[i].x), f2tf32(pb[i].y), f2tf32(pb[i].z), f2tf32(pb[i].w) };
        *reinterpret_cast<uint4*>(&sA[0][r * SMSTRIDE + scol]) = au;
        *reinterpret_cast<uint4*>(&sB[0][r * SMSTRIDE + scol]) = bu;
    }
    __syncthreads();

    const int nk = K >> 5;
    for (int kt = 0; kt < nk; kt++) {
        const int cur = kt & 1;
        const bool more = (kt + 1) < nk;

        if (more) {
            int k0 = (kt + 1) << 5;
            #pragma unroll
            for (int i = 0; i < 4; i++) {
                int r = srow + 16 * i;
                pa[i] = *reinterpret_cast<const float4*>(&A[(bm + r) * lda + k0 + scol]);
                pb[i] = *reinterpret_cast<const float4*>(&B[(bn + r) * ldb + k0 + scol]);
            }
        }

        const uint32_t* As = sA[cur];
        const uint32_t* Bs = sB[cur];
        #pragma unroll
        for (int ks = 0; ks < 4; ks++) {
            uint32_t a[2][4], b[4][2];
            const int ar = lane >> 2;
            const int ac = ks * 8 + (lane & 3);
            #pragma unroll
            for (int mt = 0; mt < 2; mt++) {
                int r = wm + mt * 16 + ar;
                a[mt][0] = As[r * SMSTRIDE + ac];
                a[mt][1] = As[(r + 8) * SMSTRIDE + ac];
                a[mt][2] = As[r * SMSTRIDE + ac + 4];
                a[mt][3] = As[(r + 8) * SMSTRIDE + ac + 4];
            }
            #pragma unroll
            for (int nt = 0; nt < 4; nt++) {
                int n = wn + nt * 8 + ar;
                b[nt][0] = Bs[n * SMSTRIDE + ac];
                b[nt][1] = Bs[n * SMSTRIDE + ac + 4];
            }
            #pragma unroll
            for (int mt = 0; mt < 2; mt++)
                #pragma unroll
                for (int nt = 0; nt < 4; nt++)
                    mma_tf32_arr(acc[mt][nt], a[mt], b[nt]);
        }

        if (more) {
            #pragma unroll
            for (int i = 0; i < 4; i++) {
                int r = srow + 16 * i;
                uint4 au = { f2tf32(pa[i].x), f2tf32(pa[i].y), f2tf32(pa[i].z), f2tf32(pa[i].w) };
                uint4 bu = { f2tf32(pb[i].x), f2tf32(pb[i].y), f2tf32(pb[i].z), f2tf32(pb[i].w) };
                *reinterpret_cast<uint4*>(&sA[cur ^ 1][r * SMSTRIDE + scol]) = au;
                *reinterpret_cast<uint4*>(&sB[cur ^ 1][r * SMSTRIDE + scol]) = bu;
            }
        }
        __syncthreads();
    }

    #pragma unroll
    for (int mt = 0; mt < 2; mt++) {
        #pragma unroll
        for (int nt = 0; nt < 4; nt++) {
            long row = bm + wm + mt * 16 + (lane >> 2);
            long col = bn + wn + nt * 8 + (lane & 3) * 2;
            float b0 = bias[col], b1 = bias[col + 1];
            float v0 = acc[mt][nt][0] + b0;
            float v1 = acc[mt][nt][1] + b1;
            float v2 = acc[mt][nt][2] + b0;
            float v3 = acc[mt][nt][3] + b1;
            if (RELU) {
                v0 = fmaxf(v0, 0.f); v1 = fmaxf(v1, 0.f);
                v2 = fmaxf(v2, 0.f); v3 = fmaxf(v3, 0.f);
            }
            *reinterpret_cast<float2*>(&C[row * ldc + col])       = make_float2(v0, v1);
            *reinterpret_cast<float2*>(&C[(row + 8) * ldc + col]) = make_float2(v2, v3);
        }
    }
}

// G3: y[b] = relu(h[b] @ Weff[b]^T + b_red)   grid(4,2,32) x 128
__global__ void __launch_bounds__(128) gemm3_kernel(const float* __restrict__ b_red)
{
    gemm_body<true>(g_h, EE, (long)SS * EE, g_weff, EE, (long)EE * EE,
                    g_y, EE, (long)SS * EE, b_red, EE);
}

// ---------------- G2: Weff[b,e,j] = sum_k s[b,k]*w_red[e, k*E+j] ----------------
__global__ void __launch_bounds__(256) weff_kernel(const float* __restrict__ w_red)
{
    __shared__ float ss[BB * SS];
    int tid = threadIdx.x;
    for (int i = tid; i < BB * SS; i += 256) ss[i] = g_s[i];
    __syncthreads();

    int e = blockIdx.x;
    const float* w = w_red + (long)e * (SS * EE) + tid;
    float acc[BB];
    #pragma unroll
    for (int b = 0; b < BB; b++) acc[b] = 0.f;

    #pragma unroll 8
    for (int k = 0; k < SS; k++) {
        float wv = w[(long)k * EE];
        #pragma unroll
        for (int b = 0; b < BB; b++) acc[b] += ss[b * SS + k] * wv;
    }
    #pragma unroll
    for (int b = 0; b < BB; b++)
        g_weff[(long)b * (EE * EE) + (long)e * EE + tid] = acc[b];
}

// ---------------- G4 split-K ----------------
__global__ void __launch_bounds__(256) red2_partial_kernel(const float* __restrict__ w_red2)
{
    __shared__ float ys[32][68];
    __shared__ float ws[64][65];
    int tid = threadIdx.x;
    int e_base = blockIdx.x * 64;
    long k_base = (long)blockIdx.y * 512;
    int el = tid & 63;
    int bb = (tid >> 6) * 8;
    float acc[8] = {};

    for (int k0 = 0; k0 < 512; k0 += 64) {
        #pragma unroll
        for (int i = 0; i < 2; i++) {
            int idx = tid + i * 256;
            int row = idx >> 4;
            int c4 = (idx & 15) * 4;
            float4 v = *reinterpret_cast<const float4*>(
                &g_y[(long)row * (SS * EE) + k_base + k0 + c4]);
            *reinterpret_cast<float4*>(&ys[row][c4]) = v;
        }
        #pragma unroll
        for (int i = 0; i < 4; i++) {
            int idx = tid + i * 256;
            int row = idx >> 4;
            int c4 = (idx & 15) * 4;
            float4 v = *reinterpret_cast<const float4*>(
                &w_red2[(long)(e_base + row) * (SS * EE) + k_base + k0 + c4]);
            ws[row][c4] = v.x; ws[row][c4 + 1] = v.y;
            ws[row][c4 + 2] = v.z; ws[row][c4 + 3] = v.w;
        }
        __syncthreads();
        #pragma unroll 8
        for (int kk = 0; kk < 64; kk++) {
            float wv = ws[el][kk];
            #pragma unroll
            for (int i = 0; i < 8; i++) acc[i] += ys[bb + i][kk] * wv;
        }
        __syncthreads();
    }
    #pragma unroll
    for (int i = 0; i < 8; i++)
        g_part[(long)blockIdx.y * (BB * EE) + (bb + i) * EE + e_base + el] = acc[i];
}

__global__ void red2_reduce_kernel(const float* __restrict__ b_red2)
{
    int idx = blockIdx.x * 256 + threadIdx.x;
    float s = b_red2[idx & 255];
    #pragma unroll 8
    for (int ks = 0; ks < 64; ks++) s += g_part[(long)ks * (BB * EE) + idx];
    g_y2[idx] = fmaxf(s, 0.f);
}

// ---------------- G5: out = y2 @ w_out^T + b_out ----------------
__global__ void __launch_bounds__(256) out_kernel(
    const float* __restrict__ w_out, const float* __restrict__ b_out,
    float* __restrict__ out)
{
    __shared__ float ys[32][68];
    __shared__ float ws[64][65];
    int tid = threadIdx.x;
    int v_base = blockIdx.x * 64;
    int vl = tid & 63;
    int bb = (tid >> 6) * 8;
    float acc[8] = {};

    for (int k0 = 0; k0 < EE; k0 += 64) {
        #pragma unroll
        for (int i = 0; i < 2; i++) {
            int idx = tid + i * 256;
            int row = idx >> 4;
            int c4 = (idx & 15) * 4;
            float4 v = *reinterpret_cast<const float4*>(&g_y2[row * EE + k0 + c4]);
            *reinterpret_cast<float4*>(&ys[row][c4]) = v;
        }
        #pragma unroll
        for (int i = 0; i < 4; i++) {
            int idx = tid + i * 256;
            int row = idx >> 4;
            int c4 = (idx & 15) * 4;
            float4 v = *reinterpret_cast<const float4*>(
                &w_out[(long)(v_base + row) * EE + k0 + c4]);
            ws[row][c4] = v.x; ws[row][c4 + 1] = v.y;
            ws[row][c4 + 2] = v.z; ws[row][c4 + 3] = v.w;
        }
        __syncthreads();
        #pragma unroll 8
        for (int kk = 0; kk < 64; kk++) {
            float wv = ws[vl][kk];
            #pragma unroll
            for (int i = 0; i < 8; i++) acc[i] += ys[bb + i][kk] * wv;
        }
        __syncthreads();
    }
    float bo = b_out[v_base + vl];
    #pragma unroll
    for (int i = 0; i < 8; i++)
        out[(long)(bb + i) * VV + v_base + vl] = acc[i] + bo;
}

// ---------------- launch ----------------
extern "C" void kernel_launch(void* const* d_in, const int* in_sizes, int n_in,
                              void* d_out, int out_size)
{
    const float* x      = (const float*)d_in[0];
    const float* w_emb  = (const float*)d_in[1];
    const float* b_emb  = (const float*)d_in[2];
    const float* w_red  = (const float*)d_in[3];
    const float* b_red  = (const float*)d_in[4];
    const float* w_red2 = (const float*)d_in[5];
    const float* b_red2 = (const float*)d_in[6];
    const float* w_out  = (const float*)d_in[7];
    const float* b_out  = (const float*)d_in[8];
    float* out = (float*)d_out;

    dummy_kernel<<<1, 32>>>();                              // shift ncu slot
    dummy_kernel<<<1, 32>>>();                              // so the profiled
    dummy_kernel<<<1, 32>>>();                              // launch is g1
    g1_kernel<<<dim3(2, 32, KSPLIT), 128>>>(x, w_emb);      // G1 partials
    h_reduce_kernel<<<MR, 256>>>(b_emb);                    // h + rowsum
    weff_kernel<<<256, 256>>>(w_red);                       // Weff
    gemm3_kernel<<<dim3(4, 2, 32), 128>>>(b_red);           // y
    red2_partial_kernel<<<dim3(4, 64), 256>>>(w_red2);      // G4 partials
    red2_reduce_kernel<<<32, 256>>>(b_red2);                // y2
    out_kernel<<<128, 256>>>(w_out, b_out, out);            // out
}

// round 11
// speedup vs baseline: 1.3754x; 1.0799x over previous
#include <cuda_runtime.h>
#include <cstdint>

// Shapes (fixed by the problem)
#define BB   32
#define SS   128
#define VV   8192
#define EE   256
#define MR   (BB*SS)

// G1 split-K config
#define KSPLIT 4
#define KCHUNK (VV/KSPLIT)   // 2048
#define BK32   32
#define STR    36            // smem row stride in uint32 (32 + 4 pad)
#define TILE_U32 (128 * STR)                 // one stage of one operand
#define G1_DSMEM (4 * TILE_U32 * 4)          // 73728 bytes

// ---------------- scratch (device globals; no allocation) ----------------
__device__ float g_p1[KSPLIT][MR][EE];  // G1 split-K partials 16 MB
__device__ float g_h[MR*EE];            // h     [4096,256]
__device__ float g_s[MR];               // rowsum(h)
__device__ float g_weff[BB*EE*EE];      // Weff  [32,256,256]
__device__ float g_y[MR*EE];            // y     [4096,256]
__device__ float g_part[64*BB*EE];      // G4 split-K partials
__device__ float g_y2[BB*EE];           // y2    [32,256]

// ---------------- helpers ----------------
__device__ __forceinline__ uint32_t f2tf32(float f) {
    uint32_t u;
    asm("cvt.rna.tf32.f32 %0, %1;" : "=r"(u) : "f"(f));
    return u;
}

__device__ __forceinline__ uint32_t smem_u32(const void* p) {
    uint32_t a;
    asm("{ .reg .u64 t; cvta.to.shared.u64 t, %1; cvt.u32.u64 %0, t; }" : "=r"(a) : "l"(p));
    return a;
}

__device__ __forceinline__ uint4 ldsm_x4(uint32_t addr) {
    uint4 r;
    asm volatile("ldmatrix.sync.aligned.m8n8.x4.shared.b16 {%0,%1,%2,%3}, [%4];"
        : "=r"(r.x), "=r"(r.y), "=r"(r.z), "=r"(r.w) : "r"(addr));
    return r;
}

__device__ __forceinline__ void mma_tf32(float c[4], const uint4 a, const uint32_t b0, const uint32_t b1) {
    asm volatile(
        "mma.sync.aligned.m16n8k8.row.col.f32.tf32.tf32.f32 "
        "{%0,%1,%2,%3}, {%4,%5,%6,%7}, {%8,%9}, {%0,%1,%2,%3};"
        : "+f"(c[0]), "+f"(c[1]), "+f"(c[2]), "+f"(c[3])
        : "r"(a.x), "r"(a.y), "r"(a.z), "r"(a.w), "r"(b0), "r"(b1));
}

// profile-slot shifter (3 launches before g1 so ncu's fixed skip lands on g1)
__global__ void dummy_kernel() {}

// ===================================================================
// G1 split-K: partial[kz] = x[:, kz*2048:+2048] @ w_emb^T chunk
// CTA tile 128m x 128n x 32k, 128 threads = 4 warps (2m x 2n),
// warp tile 64x64. Full-line staging: 8 lanes/row (128B = 1 line/row).
// Dynamic smem: [sA0][sA1][sB0][sB1], 72 KB total.
// grid (2=n, 32=m, 4=kz) = 256 CTAs, 2 CTAs/SM (one wave).
// ===================================================================
__global__ void __launch_bounds__(128, 2) g1_kernel(
    const float* __restrict__ x, const float* __restrict__ w_emb)
{
    extern __shared__ uint32_t dsm[];
    uint32_t* sA[2] = { dsm,               dsm + TILE_U32 };
    uint32_t* sB[2] = { dsm + 2*TILE_U32,  dsm + 3*TILE_U32 };

    const int tid  = threadIdx.x;
    const int lane = tid & 31;
    const int warp = tid >> 5;
    const int wm = (warp >> 1) * 64;        // 0,64
    const int wn = (warp & 1) * 64;         // 0,64
    const long bm = (long)blockIdx.y * 128;
    const long bn = (long)blockIdx.x * 128;
    const long kbase = (long)blockIdx.z * KCHUNK;

    // full-line staging: 8 lanes per row, rows srow8 + 16*i (i=0..7)
    const int srow8 = tid >> 3;             // 0..15
    const int sc8   = (tid & 7) * 4;        // float offset in row: 0,4,...,28
    const float* Abase = x + (bm + srow8) * VV + kbase + sc8;
    const float* Bbase = w_emb + (bn + srow8) * VV + kbase + sc8;
    const long rowstep = 16L * VV;          // +16 rows

    const uint32_t sAb[2] = { smem_u32(sA[0]), smem_u32(sA[1]) };
    const uint32_t sBb[2] = { smem_u32(sB[0]), smem_u32(sB[1]) };

    // ldmatrix per-lane row/col offsets (mapping validated in R5)
    const int aRow = ((lane >> 3) & 1) * 8 + (lane & 7);
    const int aCol = (lane >> 4) * 4;
    const int bRow = ((lane >> 4) & 1) * 8 + (lane & 7);
    const int bCol = ((lane >> 3) & 1) * 4;

    float acc[4][8][4] = {};
    float4 pa[8], pb[8];

    // prefetch + stage tile 0
    #pragma unroll
    for (int i = 0; i < 8; i++) {
        pa[i] = *reinterpret_cast<const float4*>(Abase + i * rowstep);
        pb[i] = *reinterpret_cast<const float4*>(Bbase + i * rowstep);
    }
    #pragma unroll
    for (int i = 0; i < 8; i++) {
        uint4 au = { f2tf32(pa[i].x), f2tf32(pa[i].y), f2tf32(pa[i].z), f2tf32(pa[i].w) };
        uint4 bu = { f2tf32(pb[i].x), f2tf32(pb[i].y), f2tf32(pb[i].z), f2tf32(pb[i].w) };
        *reinterpret_cast<uint4*>(&sA[0][(srow8 + 16 * i) * STR + sc8]) = au;
        *reinterpret_cast<uint4*>(&sB[0][(srow8 + 16 * i) * STR + sc8]) = bu;
    }
    __syncthreads();

    const int nkt = KCHUNK / BK32;          // 64
    for (int kt = 0; kt < nkt; kt++) {
        const int cur = kt & 1;
        const bool more = (kt + 1) < nkt;

        if (more) {
            const float* Ap = Abase + (kt + 1) * BK32;
            const float* Bp = Bbase + (kt + 1) * BK32;
            #pragma unroll
            for (int i = 0; i < 8; i++) {
                pa[i] = *reinterpret_cast<const float4*>(Ap + i * rowstep);
                pb[i] = *reinterpret_cast<const float4*>(Bp + i * rowstep);
            }
        }

        const uint32_t ab = sAb[cur];
        const uint32_t bb = sBb[cur];
        #pragma unroll
        for (int ks = 0; ks < 4; ks++) {
            const int k0 = ks * 8;
            uint4 af[4], bf[4];
            #pragma unroll
            for (int mi = 0; mi < 4; mi++)
                af[mi] = ldsm_x4(ab + ((wm + mi * 16 + aRow) * STR + k0 + aCol) * 4);
            #pragma unroll
            for (int q = 0; q < 4; q++)
                bf[q] = ldsm_x4(bb + ((wn + q * 16 + bRow) * STR + k0 + bCol) * 4);

            #pragma unroll
            for (int mi = 0; mi < 4; mi++) {
                #pragma unroll
                for (int nt = 0; nt < 8; nt++) {
                    const int q = nt >> 1;
                    if (nt & 1) mma_tf32(acc[mi][nt], af[mi], bf[q].z, bf[q].w);
                    else        mma_tf32(acc[mi][nt], af[mi], bf[q].x, bf[q].y);
                }
            }
        }

        if (more) {
            uint32_t* dA = sA[cur ^ 1];
            uint32_t* dB = sB[cur ^ 1];
            #pragma unroll
            for (int i = 0; i < 8; i++) {
                uint4 au = { f2tf32(pa[i].x), f2tf32(pa[i].y), f2tf32(pa[i].z), f2tf32(pa[i].w) };
                uint4 bu = { f2tf32(pb[i].x), f2tf32(pb[i].y), f2tf32(pb[i].z), f2tf32(pb[i].w) };
                *reinterpret_cast<uint4*>(&dA[(srow8 + 16 * i) * STR + sc8]) = au;
                *reinterpret_cast<uint4*>(&dB[(srow8 + 16 * i) * STR + sc8]) = bu;
            }
        }
        __syncthreads();
    }

    // epilogue: raw partials
    float* P = &g_p1[blockIdx.z][0][0];
    #pragma unroll
    for (int mi = 0; mi < 4; mi++) {
        #pragma unroll
        for (int nt = 0; nt < 8; nt++) {
            long row = bm + wm + mi * 16 + (lane >> 2);
            long col = bn + wn + nt * 8 + (lane & 3) * 2;
            *reinterpret_cast<float2*>(&P[row * EE + col]) =
                make_float2(acc[mi][nt][0], acc[mi][nt][1]);
            *reinterpret_cast<float2*>(&P[(row + 8) * EE + col]) =
                make_float2(acc[mi][nt][2], acc[mi][nt][3]);
        }
    }
}

// ---------------- h = relu(sum partials + bias); rowsum -> s ----------------
__global__ void __launch_bounds__(256) h_reduce_kernel(const float* __restrict__ b_emb)
{
    const int row = blockIdx.x;
    const int e = threadIdx.x;
    const int lane = e & 31;
    const int warp = e >> 5;

    float v = b_emb[e];
    #pragma unroll
    for (int ks = 0; ks < KSPLIT; ks++) v += g_p1[ks][row][e];
    v = fmaxf(v, 0.f);
    g_h[(long)row * EE + e] = v;

    float s = v;
    #pragma unroll
    for (int o = 16; o; o >>= 1) s += __shfl_xor_sync(0xffffffffu, s, o);
    __shared__ float red[8];
    if (lane == 0) red[warp] = s;
    __syncthreads();
    if (e == 0) {
        float t = 0.f;
        #pragma unroll
        for (int i = 0; i < 8; i++) t += red[i];
        g_s[row] = t;
    }
}

// ---------------- generic tf32 GEMM (64x64 tile, used for G3) ----------------
#define SMSTRIDE 36

__device__ __forceinline__ void mma_tf32_arr(float c[4], const uint32_t a[4], const uint32_t b[2]) {
    asm volatile(
        "mma.sync.aligned.m16n8k8.row.col.f32.tf32.tf32.f32 "
        "{%0,%1,%2,%3}, {%4,%5,%6,%7}, {%8,%9}, {%0,%1,%2,%3};"
        : "+f"(c[0]), "+f"(c[1]), "+f"(c[2]), "+f"(c[3])
        : "r"(a[0]), "r"(a[1]), "r"(a[2]), "r"(a[3]), "r"(b[0]), "r"(b[1]));
}

template <bool RELU>
__device__ __forceinline__ void gemm_body(
    const float* __restrict__ A, long lda, long strideA,
    const float* __restrict__ B, long ldb, long strideB,
    float* __restrict__ C, long ldc, long strideC,
    const float* __restrict__ bias, int K)
{
    __shared__ uint32_t sA[2][64 * SMSTRIDE];
    __shared__ uint32_t sB[2][64 * SMSTRIDE];

    const int tid  = threadIdx.x;
    const int lane = tid & 31;
    const int warp = tid >> 5;
    const int wm = (warp >> 1) * 32;
    const int wn = (warp & 1) * 32;
    const long bm = (long)blockIdx.y * 64;
    const long bn = (long)blockIdx.x * 64;

    A += (long)blockIdx.z * strideA;
    B += (long)blockIdx.z * strideB;
    C += (long)blockIdx.z * strideC;

    const int srow = tid >> 3;
    const int scol = (tid & 7) * 4;

    float acc[2][4][4] = {};
    float4 pa[4], pb[4];

    #pragma unroll
    for (int i = 0; i < 4; i++) {
        int r = srow + 16 * i;
        pa[i] = *reinterpret_cast<const float4*>(&A[(bm + r) * lda + 0 + scol]);
        pb[i] = *reinterpret_cast<const float4*>(&B[(bn + r) * ldb + 0 + scol]);
    }
    #pragma unroll
    for (int i = 0; i < 4; i++) {
        int r = srow + 16 * i;
        uint4 au = { f2tf32(pa[i].x), f2tf32(pa[i].y), f2tf32(pa[i].z), f2tf32(pa[i].w) };
        uint4 bu = { f2tf32(pb[i].x), f2tf32(pb[i].y), f2tf32(pb[i].z), f2tf32(pb[i].w) };
        *reinterpret_cast<uint4*>(&sA[0][r * SMSTRIDE + scol]) = au;
        *reinterpret_cast<uint4*>(&sB[0][r * SMSTRIDE + scol]) = bu;
    }
    __syncthreads();

    const int nk = K >> 5;
    for (int kt = 0; kt < nk; kt++) {
        const int cur = kt & 1;
        const bool more = (kt + 1) < nk;

        if (more) {
            int k0 = (kt + 1) << 5;
            #pragma unroll
            for (int i = 0; i < 4; i++) {
                int r = srow + 16 * i;
                pa[i] = *reinterpret_cast<const float4*>(&A[(bm + r) * lda + k0 + scol]);
                pb[i] = *reinterpret_cast<const float4*>(&B[(bn + r) * ldb + k0 + scol]);
            }
        }

        const uint32_t* As = sA[cur];
        const uint32_t* Bs = sB[cur];
        #pragma unroll
        for (int ks = 0; ks < 4; ks++) {
            uint32_t a[2][4], b[4][2];
            const int ar = lane >> 2;
            const int ac = ks * 8 + (lane & 3);
            #pragma unroll
            for (int mt = 0; mt < 2; mt++) {
                int r = wm + mt * 16 + ar;
                a[mt][0] = As[r * SMSTRIDE + ac];
                a[mt][1] = As[(r + 8) * SMSTRIDE + ac];
                a[mt][2] = As[r * SMSTRIDE + ac + 4];
                a[mt][3] = As[(r + 8) * SMSTRIDE + ac + 4];
            }
            #pragma unroll
            for (int nt = 0; nt < 4; nt++) {
                int n = wn + nt * 8 + ar;
                b[nt][0] = Bs[n * SMSTRIDE + ac];
                b[nt][1] = Bs[n * SMSTRIDE + ac + 4];
            }
            #pragma unroll
            for (int mt = 0; mt < 2; mt++)
                #pragma unroll
                for (int nt = 0; nt < 4; nt++)
                    mma_tf32_arr(acc[mt][nt], a[mt], b[nt]);
        }

        if (more) {
            #pragma unroll
            for (int i = 0; i < 4; i++) {
                int r = srow + 16 * i;
                uint4 au = { f2tf32(pa[i].x), f2tf32(pa[i].y), f2tf32(pa[i].z), f2tf32(pa[i].w) };
                uint4 bu = { f2tf32(pb[i].x), f2tf32(pb[i].y), f2tf32(pb[i].z), f2tf32(pb[i].w) };
                *reinterpret_cast<uint4*>(&sA[cur ^ 1][r * SMSTRIDE + scol]) = au;
                *reinterpret_cast<uint4*>(&sB[cur ^ 1][r * SMSTRIDE + scol]) = bu;
            }
        }
        __syncthreads();
    }

    #pragma unroll
    for (int mt = 0; mt < 2; mt++) {
        #pragma unroll
        for (int nt = 0; nt < 4; nt++) {
            long row = bm + wm + mt * 16 + (lane >> 2);
            long col = bn + wn + nt * 8 + (lane & 3) * 2;
            float b0 = bias[col], b1 = bias[col + 1];
            float v0 = acc[mt][nt][0] + b0;
            float v1 = acc[mt][nt][1] + b1;
            float v2 = acc[mt][nt][2] + b0;
            float v3 = acc[mt][nt][3] + b1;
            if (RELU) {
                v0 = fmaxf(v0, 0.f); v1 = fmaxf(v1, 0.f);
                v2 = fmaxf(v2, 0.f); v3 = fmaxf(v3, 0.f);
            }
            *reinterpret_cast<float2*>(&C[row * ldc + col])       = make_float2(v0, v1);
            *reinterpret_cast<float2*>(&C[(row + 8) * ldc + col]) = make_float2(v2, v3);
        }
    }
}

// G3: y[b] = relu(h[b] @ Weff[b]^T + b_red)   grid(4,2,32) x 128
__global__ void __launch_bounds__(128) gemm3_kernel(const float* __restrict__ b_red)
{
    gemm_body<true>(g_h, EE, (long)SS * EE, g_weff, EE, (long)EE * EE,
                    g_y, EE, (long)SS * EE, b_red, EE);
}

// ---------------- G2: Weff[b,e,j] = sum_k s[b,k]*w_red[e, k*E+j] ----------------
__global__ void __launch_bounds__(256) weff_kernel(const float* __restrict__ w_red)
{
    __shared__ float ss[BB * SS];
    int tid = threadIdx.x;
    for (int i = tid; i < BB * SS; i += 256) ss[i] = g_s[i];
    __syncthreads();

    int e = blockIdx.x;
    const float* w = w_red + (long)e * (SS * EE) + tid;
    float acc[BB];
    #pragma unroll
    for (int b = 0; b < BB; b++) acc[b] = 0.f;

    #pragma unroll 8
    for (int k = 0; k < SS; k++) {
        float wv = w[(long)k * EE];
        #pragma unroll
        for (int b = 0; b < BB; b++) acc[b] += ss[b * SS + k] * wv;
    }
    #pragma unroll
    for (int b = 0; b < BB; b++)
        g_weff[(long)b * (EE * EE) + (long)e * EE + tid] = acc[b];
}

// ---------------- G4 split-K ----------------
__global__ void __launch_bounds__(256) red2_partial_kernel(const float* __restrict__ w_red2)
{
    __shared__ float ys[32][68];
    __shared__ float ws[64][65];
    int tid = threadIdx.x;
    int e_base = blockIdx.x * 64;
    long k_base = (long)blockIdx.y * 512;
    int el = tid & 63;
    int bb = (tid >> 6) * 8;
    float acc[8] = {};

    for (int k0 = 0; k0 < 512; k0 += 64) {
        #pragma unroll
        for (int i = 0; i < 2; i++) {
            int idx = tid + i * 256;
            int row = idx >> 4;
            int c4 = (idx & 15) * 4;
            float4 v = *reinterpret_cast<const float4*>(
                &g_y[(long)row * (SS * EE) + k_base + k0 + c4]);
            *reinterpret_cast<float4*>(&ys[row][c4]) = v;
        }
        #pragma unroll
        for (int i = 0; i < 4; i++) {
            int idx = tid + i * 256;
            int row = idx >> 4;
            int c4 = (idx & 15) * 4;
            float4 v = *reinterpret_cast<const float4*>(
                &w_red2[(long)(e_base + row) * (SS * EE) + k_base + k0 + c4]);
            ws[row][c4] = v.x; ws[row][c4 + 1] = v.y;
            ws[row][c4 + 2] = v.z; ws[row][c4 + 3] = v.w;
        }
        __syncthreads();
        #pragma unroll 8
        for (int kk = 0; kk < 64; kk++) {
            float wv = ws[el][kk];
            #pragma unroll
            for (int i = 0; i < 8; i++) acc[i] += ys[bb + i][kk] * wv;
        }
        __syncthreads();
    }
    #pragma unroll
    for (int i = 0; i < 8; i++)
        g_part[(long)blockIdx.y * (BB * EE) + (bb + i) * EE + e_base + el] = acc[i];
}

__global__ void red2_reduce_kernel(const float* __restrict__ b_red2)
{
    int idx = blockIdx.x * 256 + threadIdx.x;
    float s = b_red2[idx & 255];
    #pragma unroll 8
    for (int ks = 0; ks < 64; ks++) s += g_part[(long)ks * (BB * EE) + idx];
    g_y2[idx] = fmaxf(s, 0.f);
}

// ---------------- G5: out = y2 @ w_out^T + b_out ----------------
__global__ void __launch_bounds__(256) out_kernel(
    const float* __restrict__ w_out, const float* __restrict__ b_out,
    float* __restrict__ out)
{
    __shared__ float ys[32][68];
    __shared__ float ws[64][65];
    int tid = threadIdx.x;
    int v_base = blockIdx.x * 64;
    int vl = tid & 63;
    int bb = (tid >> 6) * 8;
    float acc[8] = {};

    for (int k0 = 0; k0 < EE; k0 += 64) {
        #pragma unroll
        for (int i = 0; i < 2; i++) {
            int idx = tid + i * 256;
            int row = idx >> 4;
            int c4 = (idx & 15) * 4;
            float4 v = *reinterpret_cast<const float4*>(&g_y2[row * EE + k0 + c4]);
            *reinterpret_cast<float4*>(&ys[row][c4]) = v;
        }
        #pragma unroll
        for (int i = 0; i < 4; i++) {
            int idx = tid + i * 256;
            int row = idx >> 4;
            int c4 = (idx & 15) * 4;
            float4 v = *reinterpret_cast<const float4*>(
                &w_out[(long)(v_base + row) * EE + k0 + c4]);
            ws[row][c4] = v.x; ws[row][c4 + 1] = v.y;
            ws[row][c4 + 2] = v.z; ws[row][c4 + 3] = v.w;
        }
        __syncthreads();
        #pragma unroll 8
        for (int kk = 0; kk < 64; kk++) {
            float wv = ws[vl][kk];
            #pragma unroll
            for (int i = 0; i < 8; i++) acc[i] += ys[bb + i][kk] * wv;
        }
        __syncthreads();
    }
    float bo = b_out[v_base + vl];
    #pragma unroll
    for (int i = 0; i < 8; i++)
        out[(long)(bb + i) * VV + v_base + vl] = acc[i] + bo;
}

// ---------------- launch ----------------
extern "C" void kernel_launch(void* const* d_in, const int* in_sizes, int n_in,
                              void* d_out, int out_size)
{
    const float* x      = (const float*)d_in[0];
    const float* w_emb  = (const float*)d_in[1];
    const float* b_emb  = (const float*)d_in[2];
    const float* w_red  = (const float*)d_in[3];
    const float* b_red  = (const float*)d_in[4];
    const float* w_red2 = (const float*)d_in[5];
    const float* b_red2 = (const float*)d_in[6];
    const float* w_out  = (const float*)d_in[7];
    const float* b_out  = (const float*)d_in[8];
    float* out = (float*)d_out;

    cudaFuncSetAttribute(g1_kernel, cudaFuncAttributeMaxDynamicSharedMemorySize, G1_DSMEM);

    dummy_kernel<<<1, 32>>>();                                   // shift ncu slot
    dummy_kernel<<<1, 32>>>();                                   // so the profiled
    dummy_kernel<<<1, 32>>>();                                   // launch is g1
    g1_kernel<<<dim3(2, 32, KSPLIT), 128, G1_DSMEM>>>(x, w_emb); // G1 partials
    h_reduce_kernel<<<MR, 256>>>(b_emb);                         // h + rowsum
    weff_kernel<<<256, 256>>>(w_red);                            // Weff
    gemm3_kernel<<<dim3(4, 2, 32), 128>>>(b_red);                // y
    red2_partial_kernel<<<dim3(4, 64), 256>>>(w_red2);           // G4 partials
    red2_reduce_kernel<<<32, 256>>>(b_red2);                     // y2
    out_kernel<<<128, 256>>>(w_out, b_out, out);                 // out
}